// round 15
// baseline (speedup 1.0000x reference)
#include <cuda_runtime.h>
#include <cuda_bf16.h>
#include <cstdint>

#define N_NODES 100000
#define N_EDGES 1600000
#define ND 128
#define ED 48
#define GD 64
#define NG 64
#define HID 256

// ---------------- device scratch ----------------
__device__ __align__(16) float g_agg[N_NODES * ED];
__device__ __align__(16) float g_gu[NG * HID];
// W1^T tf32 blob: [11 chunks][256 n][16 k] identity layout, fp32 storage
__device__ __align__(16) float g_w1t[11 * 256 * 16];
// W2^T tf32 blob: [16 chunks][128 n][16 k]
__device__ __align__(16) float g_w2t[16 * 128 * 16];

// ---------------- helpers ----------------
__device__ __forceinline__ uint32_t smem_u32(const void* p) {
    return (uint32_t)__cvta_generic_to_shared(p);
}
__device__ __forceinline__ void cp16(char* dst, const char* src) {
    uint32_t s = smem_u32(dst);
    asm volatile("cp.async.cg.shared.global [%0], [%1], 16;" :: "r"(s), "l"(src));
}
#define CP_COMMIT asm volatile("cp.async.commit_group;")
__device__ __forceinline__ void cp_wait0() { asm volatile("cp.async.wait_group 0;"); }

__device__ __forceinline__ uint32_t f2tf(float f) {
    uint32_t r;
    asm("cvt.rna.tf32.f32 %0, %1;" : "=r"(r) : "f"(f));
    return r;
}
__device__ __forceinline__ void mma_tf32(float d[4], uint32_t a0, uint32_t a1,
                                         uint32_t a2, uint32_t a3,
                                         uint32_t b0, uint32_t b1) {
    asm volatile("mma.sync.aligned.m16n8k8.row.col.f32.tf32.tf32.f32 "
                 "{%0,%1,%2,%3}, {%4,%5,%6,%7}, {%8,%9}, {%0,%1,%2,%3};"
                 : "+f"(d[0]), "+f"(d[1]), "+f"(d[2]), "+f"(d[3])
                 : "r"(a0), "r"(a1), "r"(a2), "r"(a3), "r"(b0), "r"(b1));
}
__device__ __forceinline__ uint4 lds128(uint32_t addr) {
    uint4 v;
    asm volatile("ld.shared.v4.b32 {%0,%1,%2,%3}, [%4];"
                 : "=r"(v.x), "=r"(v.y), "=r"(v.z), "=r"(v.w) : "r"(addr));
    return v;
}
__device__ __forceinline__ float4 ldg_cs128(const float* p) {
    float4 v;
    asm volatile("ld.global.cs.v4.f32 {%0,%1,%2,%3}, [%4];"
                 : "=f"(v.x), "=f"(v.y), "=f"(v.z), "=f"(v.w) : "l"(p));
    return v;
}
// convert float4 to tf32 bits, return as float4 bit-pattern
__device__ __forceinline__ float4 tf4(float4 v) {
    float4 r;
    r.x = __uint_as_float(f2tf(v.x));
    r.y = __uint_as_float(f2tf(v.y));
    r.z = __uint_as_float(f2tf(v.z));
    r.w = __uint_as_float(f2tf(v.w));
    return r;
}

// ---------------- Kernel: scatter-add (vector red, streaming reads) ----------------
__global__ void k_scatter(const float* __restrict__ edges,
                          const int* __restrict__ recv) {
    int idx = blockIdx.x * blockDim.x + threadIdx.x;
    if (idx >= N_EDGES * 12) return;
    int e = idx / 12;
    int c = idx - e * 12;
    float4 v = ldg_cs128(edges + (size_t)idx * 4);
    int r = recv[e];
    r = min(max(r, 0), N_NODES - 1);
    float* dst = g_agg + r * ED + c * 4;
    asm volatile("red.global.add.v4.f32 [%0], {%1,%2,%3,%4};"
                 :: "l"(dst), "f"(v.x), "f"(v.y), "f"(v.z), "f"(v.w) : "memory");
}

// ---------------- zero g_agg ----------------
__global__ void k_zero() {
    int i = blockIdx.x * blockDim.x + threadIdx.x;
    if (i < (N_NODES * ED) / 4)
        reinterpret_cast<float4*>(g_agg)[i] = make_float4(0.f, 0.f, 0.f, 0.f);
}

// ---------------- W1^T | W2^T tf32 blobs (identity layouts) ----------------
// grid = 176 + 128 = 304 blocks x 256 thr
__global__ void k_blobs(const float* __restrict__ W1, const float* __restrict__ W2) {
    int b = blockIdx.x, t = threadIdx.x;
    if (b < 176) {                        // W1^T tf32 blob [11][256][16]
        int idx = b * 256 + t;            // 45056
        int p = idx & 15, n = (idx >> 4) & 255, chunk = idx >> 12;
        int kg = chunk * 16 + p;
        g_w1t[idx] = __uint_as_float(f2tf(W1[kg * HID + n]));
    } else {                              // W2^T tf32 blob [16][128][16]
        int idx = (b - 176) * 256 + t;    // 32768
        int p = idx & 15, n = (idx >> 4) & 127, chunk = idx >> 11;
        int kg = chunk * 16 + p;
        g_w2t[idx] = __uint_as_float(f2tf(W2[kg * ND + n]));
    }
}

// ---------------- gu = globals @ W1c + b1 (fp32) ----------------
__global__ void k_gu(const float* __restrict__ gg, const float* __restrict__ W1,
                     const float* __restrict__ b1) {
    __shared__ float sg[GD];
    int g = blockIdx.x, j = threadIdx.x;
    if (j < GD) sg[j] = gg[g * GD + j];
    __syncthreads();
    float acc = b1[j];
#pragma unroll
    for (int k = 0; k < GD; k++)
        acc = fmaf(sg[k], W1[(ND + ED + k) * HID + j], acc);
    g_gu[g * HID + j] = acc;
}

// ---------------- fused MLP: tf32 mma, 64 rows/block, 2 CTAs/SM ----------------
#define A_OFF  0
#define B1_OFF 46080
#define H_OFF  0
#define B2_OFF 70656
#define SMEM_BYTES 111616
#define SA_E 176
#define SH_E 272
#define NC1 11
#define NP1 6
#define NP2 8

__global__ void __launch_bounds__(256, 2) k_mlp_mma(
    const float* __restrict__ nodes, const int* __restrict__ batch,
    const float* __restrict__ b2, float* __restrict__ out) {
    extern __shared__ char smem[];
    const uint32_t sbase = smem_u32(smem);
    const int t = threadIdx.x;
    const int wid = t >> 5, lane = t & 31;
    const int m0 = blockIdx.x * 64;
    const int mw = wid >> 2;          // 0..1 -> 32-row band
    const int nw = wid & 3;           // 0..3
    const int rA = mw * 32;
    const int lq = lane >> 2;         // 0..7
    const int lr = lane & 3;          // 0..3

    auto copyB1 = [&](int kc) {
        char* dst = smem + B1_OFF + ((kc >> 1) & 1) * 32768 + (kc & 1) * 16384;
        const char* src = (const char*)g_w1t + kc * 16384;
#pragma unroll
        for (int i = 0; i < 4; i++) {
            int u = (t + i * 256) * 16;
            cp16(dst + u, src + u);
        }
    };
    auto copyB2 = [&](int kc) {
        char* dst = smem + B2_OFF + ((kc >> 1) & 1) * 16384 + (kc & 1) * 8192;
        const char* src = (const char*)g_w2t + kc * 8192;
#pragma unroll
        for (int i = 0; i < 2; i++) {
            int u = (t + i * 256) * 16;
            cp16(dst + u, src + u);
        }
    };

    copyB1(0); copyB1(1); CP_COMMIT;    // pair 0 in flight

    // hoist batch reads (600-cyc gmem latency hidden behind phase 1)
    const int r0e = rA + lq;            // epilogue row base (mi=0)
    int g0a = batch[min(m0 + r0e, N_NODES - 1)];
    int g1a = batch[min(m0 + r0e + 8, N_NODES - 1)];
    int g0b = batch[min(m0 + r0e + 16, N_NODES - 1)];
    int g1b = batch[min(m0 + r0e + 24, N_NODES - 1)];
    g0a = min(max(g0a, 0), NG - 1); g1a = min(max(g1a, 0), NG - 1);
    g0b = min(max(g0b, 0), NG - 1); g1b = min(max(g1b, 0), NG - 1);

    // ---- stage X = [nodes | agg] -> A smem (tf32 bits, identity, STS.128) ----
    {
        float4* A4 = (float4*)(smem + A_OFF);   // SA_E=176 -> float4 stride 44
#pragma unroll
        for (int i = 0; i < 8; i++) {             // nodes: 64 rows x 32 quads
            int f4 = t + i * 256;
            int row = f4 >> 5, qq = f4 & 31;
            int gr = m0 + row;
            float4 v = make_float4(0.f, 0.f, 0.f, 0.f);
            if (gr < N_NODES) v = reinterpret_cast<const float4*>(nodes + (size_t)gr * ND)[qq];
            A4[row * 44 + qq] = tf4(v);
        }
#pragma unroll
        for (int i = 0; i < 3; i++) {             // agg: 64 rows x 12 quads (k 128..175)
            int f4 = t + i * 256;
            if (f4 < 768) {
                int row = f4 / 12, j = f4 - row * 12;
                int gr = m0 + row;
                float4 v = make_float4(0.f, 0.f, 0.f, 0.f);
                if (gr < N_NODES) v = reinterpret_cast<const float4*>(g_agg + (size_t)gr * ED)[j];
                A4[row * 44 + 32 + j] = tf4(v);
            }
        }
    }

    // per-lane fragment addresses (bytes)
    const uint32_t aBase = sbase + A_OFF + (rA + lq) * (SA_E * 4) + lr * 16;
    const uint32_t b1Base = sbase + B1_OFF + (nw * 64 + lq) * 64 + lr * 16;
    const uint32_t b2Base = sbase + B2_OFF + (nw * 32 + lq) * 64 + lr * 16;

    // ---------------- Phase 1: warp tile 32x64, 6 pair-iterations ----------------
    float acc[2][8][4];
#pragma unroll
    for (int a = 0; a < 2; a++)
#pragma unroll
        for (int b = 0; b < 8; b++)
#pragma unroll
            for (int c = 0; c < 4; c++) acc[a][b][c] = 0.f;

#pragma unroll
    for (int p = 0; p < NP1; ++p) {
        cp_wait0();
        __syncthreads();
        if (p < NP1 - 1) {
            copyB1(2 * p + 2);
            if (2 * p + 3 < NC1) copyB1(2 * p + 3);
            CP_COMMIT;
        }
        const int kc0 = 2 * p, kc1 = 2 * p + 1;
        const bool has1 = (kc1 < NC1);
        uint4 va0[2][2], va1[2][2];
#pragma unroll
        for (int mi = 0; mi < 2; mi++) {
            va0[mi][0] = lds128(aBase + (mi * 16) * (SA_E * 4) + kc0 * 64);
            va0[mi][1] = lds128(aBase + (mi * 16 + 8) * (SA_E * 4) + kc0 * 64);
        }
        if (has1) {
#pragma unroll
            for (int mi = 0; mi < 2; mi++) {
                va1[mi][0] = lds128(aBase + (mi * 16) * (SA_E * 4) + kc1 * 64);
                va1[mi][1] = lds128(aBase + (mi * 16 + 8) * (SA_E * 4) + kc1 * 64);
            }
        }
        uint32_t bBuf0 = (uint32_t)(p & 1) * 32768;
#pragma unroll
        for (int j = 0; j < 8; j++) {
            uint4 vb = lds128(b1Base + bBuf0 + j * 512);
#pragma unroll
            for (int mi = 0; mi < 2; mi++) {
                mma_tf32(acc[mi][j], va0[mi][0].x, va0[mi][1].x,
                         va0[mi][0].y, va0[mi][1].y, vb.x, vb.y);
                mma_tf32(acc[mi][j], va0[mi][0].z, va0[mi][1].z,
                         va0[mi][0].w, va0[mi][1].w, vb.z, vb.w);
            }
        }
        if (has1) {
            uint32_t bBuf1 = bBuf0 + 16384;
#pragma unroll
            for (int j = 0; j < 8; j++) {
                uint4 vb = lds128(b1Base + bBuf1 + j * 512);
#pragma unroll
                for (int mi = 0; mi < 2; mi++) {
                    mma_tf32(acc[mi][j], va1[mi][0].x, va1[mi][1].x,
                             va1[mi][0].y, va1[mi][1].y, vb.x, vb.y);
                    mma_tf32(acc[mi][j], va1[mi][0].z, va1[mi][1].z,
                             va1[mi][0].w, va1[mi][1].w, vb.z, vb.w);
                }
            }
        }
    }
    __syncthreads();          // A/B1 reads done; regions reusable

    copyB2(0); copyB2(1); CP_COMMIT;   // pair 0; overlaps epilogue 1

    // ---- Epilogue 1: +gu[batch], ReLU, tf32-cvt -> H smem (identity, float2) ----
    {
        float* H = (float*)(smem + H_OFF);
#pragma unroll
        for (int mi = 0; mi < 2; mi++) {
            int r0 = rA + mi * 16 + lq;
            int r1 = r0 + 8;
            const float* gu0 = g_gu + (mi ? g0b : g0a) * HID;
            const float* gu1 = g_gu + (mi ? g1b : g1a) * HID;
#pragma unroll
            for (int nf = 0; nf < 8; nf++) {
                int c = nw * 64 + nf * 8 + lr * 2;
                float2 u0 = *(const float2*)(gu0 + c);
                float2 u1 = *(const float2*)(gu1 + c);
                float2 h0, h1;
                h0.x = __uint_as_float(f2tf(fmaxf(acc[mi][nf][0] + u0.x, 0.f)));
                h0.y = __uint_as_float(f2tf(fmaxf(acc[mi][nf][1] + u0.y, 0.f)));
                h1.x = __uint_as_float(f2tf(fmaxf(acc[mi][nf][2] + u1.x, 0.f)));
                h1.y = __uint_as_float(f2tf(fmaxf(acc[mi][nf][3] + u1.y, 0.f)));
                *(float2*)(H + r0 * SH_E + c) = h0;
                *(float2*)(H + r1 * SH_E + c) = h1;
            }
        }
    }

    // ---------------- Phase 2: warp tile 32x32, 8 pair-iterations ----------------
    const uint32_t hBase = sbase + H_OFF + (rA + lq) * (SH_E * 4) + lr * 16;

    float acc2[2][4][4];
#pragma unroll
    for (int a = 0; a < 2; a++)
#pragma unroll
        for (int b = 0; b < 4; b++)
#pragma unroll
            for (int c = 0; c < 4; c++) acc2[a][b][c] = 0.f;

#pragma unroll
    for (int p = 0; p < NP2; ++p) {
        cp_wait0();
        __syncthreads();      // also publishes H at p=0
        if (p < NP2 - 1) { copyB2(2 * p + 2); copyB2(2 * p + 3); CP_COMMIT; }
        const int kc0 = 2 * p, kc1 = 2 * p + 1;
        uint4 va0[2][2], va1[2][2];
#pragma unroll
        for (int mi = 0; mi < 2; mi++) {
            va0[mi][0] = lds128(hBase + (mi * 16) * (SH_E * 4) + kc0 * 64);
            va0[mi][1] = lds128(hBase + (mi * 16 + 8) * (SH_E * 4) + kc0 * 64);
            va1[mi][0] = lds128(hBase + (mi * 16) * (SH_E * 4) + kc1 * 64);
            va1[mi][1] = lds128(hBase + (mi * 16 + 8) * (SH_E * 4) + kc1 * 64);
        }
        uint32_t bBuf0 = (uint32_t)(p & 1) * 16384;
#pragma unroll
        for (int j = 0; j < 4; j++) {
            uint4 vb = lds128(b2Base + bBuf0 + j * 512);
#pragma unroll
            for (int mi = 0; mi < 2; mi++) {
                mma_tf32(acc2[mi][j], va0[mi][0].x, va0[mi][1].x,
                         va0[mi][0].y, va0[mi][1].y, vb.x, vb.y);
                mma_tf32(acc2[mi][j], va0[mi][0].z, va0[mi][1].z,
                         va0[mi][0].w, va0[mi][1].w, vb.z, vb.w);
            }
        }
        uint32_t bBuf1 = bBuf0 + 8192;
#pragma unroll
        for (int j = 0; j < 4; j++) {
            uint4 vb = lds128(b2Base + bBuf1 + j * 512);
#pragma unroll
            for (int mi = 0; mi < 2; mi++) {
                mma_tf32(acc2[mi][j], va1[mi][0].x, va1[mi][1].x,
                         va1[mi][0].y, va1[mi][1].y, vb.x, vb.y);
                mma_tf32(acc2[mi][j], va1[mi][0].z, va1[mi][1].z,
                         va1[mi][0].w, va1[mi][1].w, vb.z, vb.w);
            }
        }
    }

    // ---- Epilogue 2: + b2, store ----
    {
        int colB = nw * 32 + lr * 2;
#pragma unroll
        for (int mi = 0; mi < 2; mi++) {
            int r0 = rA + mi * 16 + lq;
            int gr0 = m0 + r0, gr1 = gr0 + 8;
#pragma unroll
            for (int nf = 0; nf < 4; nf++) {
                int col = colB + nf * 8;
                float2 bv = *(const float2*)(b2 + col);
                if (gr0 < N_NODES) {
                    float2 o = {acc2[mi][nf][0] + bv.x, acc2[mi][nf][1] + bv.y};
                    *(float2*)(out + (size_t)gr0 * ND + col) = o;
                }
                if (gr1 < N_NODES) {
                    float2 o = {acc2[mi][nf][2] + bv.x, acc2[mi][nf][3] + bv.y};
                    *(float2*)(out + (size_t)gr1 * ND + col) = o;
                }
            }
        }
    }
}

// ---------------- launch ----------------
extern "C" void kernel_launch(void* const* d_in, const int* in_sizes, int n_in,
                              void* d_out, int out_size) {
    const float* nodes   = (const float*)d_in[0];
    const float* edges   = (const float*)d_in[1];
    const int*   eindex  = (const int*)d_in[2];
    const int*   batch   = (const int*)d_in[3];
    const float* globals = (const float*)d_in[4];
    const float* W1      = (const float*)d_in[5];
    const float* b1      = (const float*)d_in[6];
    const float* W2      = (const float*)d_in[7];
    const float* b2      = (const float*)d_in[8];
    float*       out     = (float*)d_out;

    // launch order puts k_scatter in the 4th slot (ncu capture)
    k_zero<<<(N_NODES * ED / 4 + 255) / 256, 256>>>();
    k_blobs<<<304, 256>>>(W1, W2);
    k_gu<<<NG, HID>>>(globals, W1, b1);
    k_scatter<<<(N_EDGES * 12) / 256, 256>>>(edges, eindex + N_EDGES);

    cudaFuncSetAttribute(k_mlp_mma, cudaFuncAttributeMaxDynamicSharedMemorySize, SMEM_BYTES);
    k_mlp_mma<<<(N_NODES + 63) / 64, 256, SMEM_BYTES>>>(nodes, batch, b2, out);
}